// round 15
// baseline (speedup 1.0000x reference)
#include <cuda_runtime.h>
#include <cstdint>
#include <math.h>

#define B_ 16
#define S_ 4096
#define DQ_ 1024
#define DM_ 512
#define DO_ 1024
#define H_ 16
#define D_ 64

typedef unsigned long long u64;

// -------- scratch (no allocs allowed) --------
__device__ float g_q[B_ * DO_];              // scaled query projections [b][h*64+d]
__device__ float g_ut[B_ * DM_ * H_];        // folded key proj [b][m][h]
__device__ float g_cp[16 * B_ * H_ * DM_];   // per-s-tile partials [p][b][h][m]
__device__ float g_Z[B_ * H_];               // softmax denominators

// -------- packed fp32x2 helpers --------
__device__ __forceinline__ u64 pack2(float lo, float hi) {
    u64 r; asm("mov.b64 %0, {%1,%2};" : "=l"(r) : "f"(lo), "f"(hi)); return r;
}
__device__ __forceinline__ void unpack2(u64 v, float& lo, float& hi) {
    asm("mov.b64 {%0,%1}, %2;" : "=f"(lo), "=f"(hi) : "l"(v));
}
__device__ __forceinline__ void ffma2(u64& d, u64 a, u64 b) {
    asm("fma.rn.f32x2 %0, %1, %2, %3;" : "=l"(d) : "l"(a), "l"(b), "l"(d));
}
__device__ __forceinline__ u64 add2(u64 a, u64 b) {
    u64 r; asm("add.rn.f32x2 %0, %1, %2;" : "=l"(r) : "l"(a), "l"(b)); return r;
}
__device__ __forceinline__ u64 shflx64(u64 v, int m) {
    return __shfl_xor_sync(0xFFFFFFFFu, v, m);
}

// ============================================================
// Kernel 0: zero g_q, g_Z, context slice of out. grid 64, block 256
// ============================================================
__global__ __launch_bounds__(256) void k_zero(float* __restrict__ out) {
    int i = blockIdx.x * 256 + threadIdx.x;
    if (i < B_ * DO_) { g_q[i] = 0.f; out[i] = 0.f; }
    if (i < B_ * H_) g_Z[i] = 0.f;
}

// ============================================================
// Kernel 1: q partial, Wq read once. grid (4,16), block 256
// ============================================================
__global__ __launch_bounds__(256) void k_qproj(const float* __restrict__ src,
                                               const float* __restrict__ Wq) {
    __shared__ float s_src[B_][64];
    int t = threadIdx.x;
    int o = blockIdx.x * 256 + t;
    int k0 = blockIdx.y * 64;
#pragma unroll
    for (int i = 0; i < 4; ++i) {
        int idx = i * 256 + t;
        s_src[idx >> 6][idx & 63] = src[(size_t)(idx >> 6) * DQ_ + k0 + (idx & 63)];
    }
    __syncthreads();
    float acc[B_];
#pragma unroll
    for (int b = 0; b < B_; ++b) acc[b] = 0.f;
#pragma unroll 4
    for (int k = 0; k < 64; ++k) {
        float wq = Wq[(size_t)(k0 + k) * DO_ + o];
#pragma unroll
        for (int b = 0; b < B_; ++b) acc[b] = fmaf(s_src[b][k], wq, acc[b]);
    }
#pragma unroll
    for (int b = 0; b < B_; ++b) atomicAdd(&g_q[b * DO_ + o], acc[b] * 0.125f);
}

// ============================================================
// Kernel 2: u[b,m,h] = sum_d Wk[m,h*64+d]*q[b,h,d], Wk read ONCE.
// grid (H, DM/32=16), block 128. Thread = (m in 32, b-group of 4).
// ============================================================
__global__ __launch_bounds__(128) void k_uproj(const float* __restrict__ Wk) {
    __shared__ float wk_s[32][65];
    __shared__ float q_s[B_][65];
    int h = blockIdx.x;
    int m0 = blockIdx.y * 32;
    int t = threadIdx.x;
    // stage Wk tile [32 m][64 d]
#pragma unroll
    for (int i = 0; i < 16; ++i) {
        int idx = i * 128 + t;
        int row = idx >> 6, dd = idx & 63;
        wk_s[row][dd] = Wk[(size_t)(m0 + row) * DO_ + h * D_ + dd];
    }
    // stage q for all b at this h
#pragma unroll
    for (int i = 0; i < 8; ++i) {
        int idx = i * 128 + t;
        q_s[idx >> 6][idx & 63] = g_q[(size_t)(idx >> 6) * DO_ + h * D_ + (idx & 63)];
    }
    __syncthreads();
    int mm = t & 31, bg = t >> 5;     // 4 b each
    float acc[4] = {0.f, 0.f, 0.f, 0.f};
#pragma unroll 8
    for (int d = 0; d < D_; ++d) {
        float wv = wk_s[mm][d];
#pragma unroll
        for (int j = 0; j < 4; ++j) acc[j] = fmaf(q_s[bg * 4 + j][d], wv, acc[j]);
    }
#pragma unroll
    for (int j = 0; j < 4; ++j)
        g_ut[((size_t)(bg * 4 + j) * DM_ + m0 + mm) * H_ + h] = acc[j];
}

// ============================================================
// Kernel 3: e[b,h,s] = exp(score) (masked->0), Z accumulated.
// TS=64, block 128 (4 autonomous warps, 16 s each). grid (64,B)=1024 CTAs.
// Warp-private smem slabs; NO CTA barrier in main loop.
// Thread = 2s x 16h, k-split 4 in warp. smem ~19KB.
// ============================================================
#define TS3 64
#define KC3 32
__global__ __launch_bounds__(128, 6) void k_scores(const float* __restrict__ mb,
                                                   float* __restrict__ attn,
                                                   const int* __restrict__ mask) {
    __shared__ float u_s[4][KC3 * 20];   // per-warp u chunk, pitch 20
    __shared__ float mb_s[4][16 * 34];   // per-warp mb rows, pitch 34
    __shared__ float s_Z[H_];

    int b = blockIdx.y, s_tile = blockIdx.x * TS3;
    int t = threadIdx.x, w = t >> 5, l = t & 31;
    int sg = l & 7, kg = l >> 3;

    const float* mb_b = mb + ((size_t)b * S_ + s_tile + w * 16) * DM_;
    const float* u_b = g_ut + (size_t)b * DM_ * H_;
    float* uw = &u_s[w][0];
    float* mw = &mb_s[w][0];
    if (t < H_) s_Z[t] = 0.f;
    __syncthreads();

    u64 acc[2][8];
#pragma unroll
    for (int j = 0; j < 2; ++j)
#pragma unroll
        for (int p = 0; p < 8; ++p) acc[j][p] = 0ull;

    for (int ch = 0; ch < DM_ / KC3; ++ch) {
        __syncwarp();
        // stage warp's 16 mb rows x 32 floats (4 rows x 128B per LDG op)
#pragma unroll
        for (int i = 0; i < 4; ++i) {
            int row = i * 4 + (l >> 3), f4 = l & 7;
            float4 v = *reinterpret_cast<const float4*>(
                mb_b + (size_t)row * DM_ + ch * KC3 + f4 * 4);
            float* d = mw + row * 34 + f4 * 4;
            d[0] = v.x; d[1] = v.y; d[2] = v.z; d[3] = v.w;
        }
        // stage warp-private u chunk: 32 k x 16 h (coalesced)
#pragma unroll
        for (int i = 0; i < 4; ++i) {
            int fidx = i * 32 + l;
            int k = fidx >> 2, hq = fidx & 3;
            float4 v = *reinterpret_cast<const float4*>(
                u_b + (size_t)(ch * KC3 + k) * H_ + hq * 4);
            *reinterpret_cast<float4*>(uw + k * 20 + hq * 4) = v;
        }
        __syncwarp();
#pragma unroll
        for (int ki = 0; ki < 8; ++ki) {
            int kk = ki * 4 + kg;
            ulonglong2 uA = *reinterpret_cast<const ulonglong2*>(uw + kk * 20);
            ulonglong2 uB = *reinterpret_cast<const ulonglong2*>(uw + kk * 20 + 4);
            ulonglong2 uC = *reinterpret_cast<const ulonglong2*>(uw + kk * 20 + 8);
            ulonglong2 uD = *reinterpret_cast<const ulonglong2*>(uw + kk * 20 + 12);
#pragma unroll
            for (int j = 0; j < 2; ++j) {
                float mv = mw[(sg * 2 + j) * 34 + kk];
                u64 d = pack2(mv, mv);
                ffma2(acc[j][0], uA.x, d); ffma2(acc[j][1], uA.y, d);
                ffma2(acc[j][2], uB.x, d); ffma2(acc[j][3], uB.y, d);
                ffma2(acc[j][4], uC.x, d); ffma2(acc[j][5], uC.y, d);
                ffma2(acc[j][6], uD.x, d); ffma2(acc[j][7], uD.y, d);
            }
        }
    }

    // k-split reduction (xor 8, 16)
#pragma unroll
    for (int j = 0; j < 2; ++j)
#pragma unroll
        for (int p = 0; p < 8; ++p) {
            u64 v = acc[j][p];
            v = add2(v, shflx64(v, 8));
            v = add2(v, shflx64(v, 16));
            acc[j][p] = v;
        }

    // epilogue: thread s = s_tile + w*16 + sg*2 + j, h = kg*4..kg*4+3
    int sbase = s_tile + w * 16 + sg * 2;
    int2 mk = *reinterpret_cast<const int2*>(mask + (size_t)b * S_ + sbase);
    int mki[2] = {mk.x, mk.y};
    float e[4][2];
    float zh[4] = {0.f, 0.f, 0.f, 0.f};
#pragma unroll
    for (int j = 0; j < 2; ++j) {
#pragma unroll
        for (int hl = 0; hl < 4; ++hl) {
            float lo, hi;
            unpack2(acc[j][kg * 2 + (hl >> 1)], lo, hi);
            float sc = (hl & 1) ? hi : lo;
            float ev = mki[j] ? 0.f : __expf(sc);
            e[hl][j] = ev;
            zh[hl] += ev;
        }
    }
#pragma unroll
    for (int hl = 0; hl < 4; ++hl) {
        *reinterpret_cast<float2*>(
            attn + (size_t)(b * H_ + kg * 4 + hl) * S_ + sbase) =
            make_float2(e[hl][0], e[hl][1]);
        zh[hl] += __shfl_xor_sync(0xFFFFFFFFu, zh[hl], 1);
        zh[hl] += __shfl_xor_sync(0xFFFFFFFFu, zh[hl], 2);
        zh[hl] += __shfl_xor_sync(0xFFFFFFFFu, zh[hl], 4);
    }
    if (sg == 0) {
#pragma unroll
        for (int hl = 0; hl < 4; ++hl) atomicAdd(&s_Z[kg * 4 + hl], zh[hl]);
    }
    __syncthreads();
    if (t < H_) atomicAdd(&g_Z[b * H_ + t], s_Z[t]);
}

// ============================================================
// Kernel 4: partial c: g_cp[stile,b,h,m] = sum_{s in tile} e*mb
// MT=64, 256 s/CTA. grid (8, 16, B) = 2048 CTAs, block 128.
// Warp w: m-half (w&1), chunk parity (w>>1). Warp-private mb slabs.
// Thread = 2m x 16h, s-split 2 (sk = l>>4). STG.64 outputs, NO atomics.
// ============================================================
#define MT5 64
#define SC5 32
__global__ __launch_bounds__(128, 6) void k_ctxacc(const float* __restrict__ mb,
                                                   const float* __restrict__ attn) {
    __shared__ float a_s[256 * 20];      // e tile, pitch 20 (LDS.128-able)
    __shared__ float mb_s[4][SC5 * 33];  // per-warp mb chunk, pitch 33

    int m_base = blockIdx.x * MT5;
    int stile = blockIdx.y;
    int s_base = stile * 256;
    int b = blockIdx.z;
    int t = threadIdx.x, w = t >> 5, l = t & 31;
    int mg = l & 15, sk = l >> 4;
    int mhalf = w & 1, spar = w >> 1;
    int m0 = mhalf * 32 + mg * 2;

    const float* mb_b = mb + ((size_t)b * S_ + s_base) * DM_ + m_base;
    const float* a_b = attn + (size_t)b * H_ * S_ + s_base;
    float* mw = &mb_s[w][0];

    // stage e tile: 256 s x 16 h (gmem-coalesced per h row)
#pragma unroll
    for (int i = 0; i < 32; ++i) {
        int idx = i * 128 + t;
        a_s[(idx & 255) * 20 + (idx >> 8)] = a_b[(size_t)(idx >> 8) * S_ + (idx & 255)];
    }
    __syncthreads();

    u64 acc[2][8];
#pragma unroll
    for (int j = 0; j < 2; ++j)
#pragma unroll
        for (int p = 0; p < 8; ++p) acc[j][p] = 0ull;

    for (int c4 = 0; c4 < 4; ++c4) {
        int ch = c4 * 2 + spar;
        __syncwarp();
        // stage warp's mb chunk: 32 s x 32 m (its m-half)
#pragma unroll
        for (int i = 0; i < 8; ++i) {
            int row = (l >> 2) + (i & 3) * 8;
            int f4 = (l & 3) + (i >> 2) * 4;
            float4 v = *reinterpret_cast<const float4*>(
                mb_b + (size_t)(ch * SC5 + row) * DM_ + mhalf * 32 + f4 * 4);
            float* d = mw + row * 33 + f4 * 4;
            d[0] = v.x; d[1] = v.y; d[2] = v.z; d[3] = v.w;
        }
        __syncwarp();
#pragma unroll
        for (int ki = 0; ki < 16; ++ki) {
            int ss = ki * 2 + sk;
            const float* ar = a_s + (ch * SC5 + ss) * 20;
            ulonglong2 aA = *reinterpret_cast<const ulonglong2*>(ar);
            ulonglong2 aB = *reinterpret_cast<const ulonglong2*>(ar + 4);
            ulonglong2 aC = *reinterpret_cast<const ulonglong2*>(ar + 8);
            ulonglong2 aD = *reinterpret_cast<const ulonglong2*>(ar + 12);
#pragma unroll
            for (int j = 0; j < 2; ++j) {
                float mv = mw[ss * 33 + mg * 2 + j];
                u64 d = pack2(mv, mv);
                ffma2(acc[j][0], aA.x, d); ffma2(acc[j][1], aA.y, d);
                ffma2(acc[j][2], aB.x, d); ffma2(acc[j][3], aB.y, d);
                ffma2(acc[j][4], aC.x, d); ffma2(acc[j][5], aC.y, d);
                ffma2(acc[j][6], aD.x, d); ffma2(acc[j][7], aD.y, d);
            }
        }
    }

    // s-split reduction (xor 16)
#pragma unroll
    for (int j = 0; j < 2; ++j)
#pragma unroll
        for (int p = 0; p < 8; ++p) acc[j][p] = add2(acc[j][p], shflx64(acc[j][p], 16));

    // Combine chunk parities across warp pairs via smem (reuse a_s).
    // spar=0 warps store; spar=1 warps add + STG.64 (each output once).
    {
        float* red = a_s;  // 5120 floats >= 16*64 = 1024 needed
        __syncthreads();
#pragma unroll
        for (int hh = 0; hh < 8; ++hh) {
            int h = sk * 8 + hh;
            int p = sk * 4 + (hh >> 1);
#pragma unroll
            for (int j = 0; j < 2; ++j) {
                float lo, hi;
                unpack2(acc[j][p], lo, hi);
                float v = (hh & 1) ? hi : lo;
                if (spar == 0) red[(h * MT5) + mhalf * 32 + mg * 2 + j] = v;
            }
        }
        __syncthreads();
        if (spar == 1) {
#pragma unroll
            for (int hh = 0; hh < 8; ++hh) {
                int h = sk * 8 + hh;
                int p = sk * 4 + (hh >> 1);
                float v0, v1;
                float lo, hi;
                unpack2(acc[0][p], lo, hi);
                v0 = ((hh & 1) ? hi : lo) + red[h * MT5 + mhalf * 32 + mg * 2 + 0];
                unpack2(acc[1][p], lo, hi);
                v1 = ((hh & 1) ? hi : lo) + red[h * MT5 + mhalf * 32 + mg * 2 + 1];
                *reinterpret_cast<float2*>(
                    g_cp + (((size_t)stile * B_ + b) * H_ + h) * DM_ + m_base + m0) =
                    make_float2(v0, v1);
            }
        }
    }
}

// ============================================================
// Kernel 5: normalize attn rows by Z. grid B*H, block 256
// ============================================================
__global__ __launch_bounds__(256) void k_norm(float* __restrict__ attn) {
    int bh = blockIdx.x;
    float inv = 1.f / g_Z[bh];
    float4* row = reinterpret_cast<float4*>(attn + (size_t)bh * S_);
#pragma unroll
    for (int i = 0; i < 4; ++i) {
        float4 v = row[threadIdx.x + i * 256];
        v.x *= inv; v.y *= inv; v.z *= inv; v.w *= inv;
        row[threadIdx.x + i * 256] = v;
    }
}

// ============================================================
// Kernel 6: context[b,h*64+d] += (1/Z) * sum_m (sum_p g_cp[p,b,h,m]) * Wv[m,h*64+d]
// grid (H, 8), block 256
// ============================================================
__global__ __launch_bounds__(256) void k_ctx(const float* __restrict__ Wv,
                                             float* __restrict__ out) {
    __shared__ float wv_s[64][65];
    __shared__ float c_s[B_][64];
    __shared__ float iz_s[B_];
    int h = blockIdx.x;
    int m0 = blockIdx.y * 64;
    int t = threadIdx.x;
    if (t < B_) iz_s[t] = 1.f / g_Z[t * H_ + h];
#pragma unroll
    for (int i = 0; i < 16; ++i) {
        int idx = i * 256 + t;
        wv_s[idx >> 6][idx & 63] = Wv[(size_t)(m0 + (idx >> 6)) * DO_ + h * D_ + (idx & 63)];
    }
#pragma unroll
    for (int i = 0; i < 4; ++i) {
        int idx = i * 256 + t;
        int bb = idx >> 6, mm = idx & 63;
        float sum = 0.f;
#pragma unroll
        for (int p = 0; p < 16; ++p)
            sum += g_cp[(((size_t)p * B_ + bb) * H_ + h) * DM_ + m0 + mm];
        c_s[bb][mm] = sum;
    }
    __syncthreads();
    int d = t & 63, bg = t >> 6;
    float acc[4] = {0.f, 0.f, 0.f, 0.f};
#pragma unroll 8
    for (int mm = 0; mm < 64; ++mm) {
        float wv = wv_s[mm][d];
#pragma unroll
        for (int j = 0; j < 4; ++j) acc[j] = fmaf(c_s[bg + j * 4][mm], wv, acc[j]);
    }
#pragma unroll
    for (int j = 0; j < 4; ++j)
        atomicAdd(&out[(size_t)(bg + j * 4) * DO_ + h * D_ + d],
                  acc[j] * iz_s[bg + j * 4]);
}

// ============================================================
extern "C" void kernel_launch(void* const* d_in, const int* in_sizes, int n_in,
                              void* d_out, int out_size) {
    const float* src = (const float*)d_in[0];
    const float* mb = (const float*)d_in[1];
    const float* Wq = (const float*)d_in[2];
    const float* Wk = (const float*)d_in[3];
    const float* Wv = (const float*)d_in[4];
    const int* mask = (const int*)d_in[5];
    float* out = (float*)d_out;
    float* attn = out + B_ * DO_;  // context first, then attn [B,H,S]

    k_zero<<<64, 256>>>(out);
    k_qproj<<<dim3(DO_ / 256, DQ_ / 64), 256>>>(src, Wq);
    k_uproj<<<dim3(H_, DM_ / 32), 128>>>(Wk);
    k_scores<<<dim3(S_ / TS3, B_), 128>>>(mb, attn, mask);
    k_ctxacc<<<dim3(DM_ / MT5, S_ / 256, B_), 128>>>(mb, attn);  // raw e
    k_norm<<<B_ * H_, 256>>>(attn);
    k_ctx<<<dim3(H_, DM_ / 64), 256>>>(Wv, out);
}